// round 1
// baseline (speedup 1.0000x reference)
#include <cuda_runtime.h>
#include <cuda_bf16.h>
#include <cstdint>

// Problem shape (fixed for this bench)
#define B_  32
#define L_  512
#define D_  768
#define H_  100
#define C_  45
#define M_  (B_ * L_)        // 16384 output rows
#define NPAD 48              // padded column count (45 -> 48)

// GEMM tiling
#define BM 128               // rows per block
#define BK 64                // k-chunk
#define THREADS 256          // (16 col-groups) x (16 row-groups)

// Scratch (device globals — no allocation allowed)
__device__ float g_WcT[D_ * NPAD];   // fused weight, k-major: [d][c], 768x48
__device__ float g_cvec[NPAD];       // fused bias: W2@b1 + b2
__device__ int   g_gather[M_];       // per output row: source token index or -1

// ---------------------------------------------------------------------------
// Kernel 1: per-batch compaction indices. One block per batch, 512 threads.
// gather[b*L + j] = index of j-th valid token in batch b, else -1.
// ---------------------------------------------------------------------------
__global__ void compact_kernel(const int* __restrict__ valid_ids) {
    __shared__ int s[L_];
    const int b = blockIdx.x;
    const int t = threadIdx.x;
    const int v = (valid_ids[b * L_ + t] == 1) ? 1 : 0;
    s[t] = v;
    __syncthreads();
    // Hillis-Steele inclusive scan over 512
#pragma unroll
    for (int off = 1; off < L_; off <<= 1) {
        int x = (t >= off) ? s[t - off] : 0;
        __syncthreads();
        s[t] += x;
        __syncthreads();
    }
    g_gather[b * L_ + t] = -1;
    __syncthreads();   // orders the -1 stores before the scatter (block-wide)
    if (v) g_gather[b * L_ + (s[t] - 1)] = t;
}

// ---------------------------------------------------------------------------
// Kernel 2: fuse the two linear layers.
//   WcT[d][c] = sum_h W2[c][h] * W1[h][d]      (stored k-major, padded to 48)
//   cvec[c]   = sum_h W2[c][h] * b1[h] + b2[c]
// grid = 768 blocks (one per d), 48 threads (one per padded c).
// ---------------------------------------------------------------------------
__global__ void fuse_kernel(const float* __restrict__ W1,
                            const float* __restrict__ b1,
                            const float* __restrict__ W2,
                            const float* __restrict__ b2) {
    const int d = blockIdx.x;
    const int c = threadIdx.x;           // 0..47
    float s = 0.0f;
    if (c < C_) {
#pragma unroll 4
        for (int h = 0; h < H_; h++)
            s += W2[c * H_ + h] * W1[h * D_ + d];   // W1 read broadcast across threads
    }
    g_WcT[d * NPAD + c] = s;
    if (d == 0) {
        float cv = 0.0f;
        if (c < C_) {
            for (int h = 0; h < H_; h++) cv += W2[c * H_ + h] * b1[h];
            cv += b2[c];
        }
        g_cvec[c] = cv;
    }
}

// ---------------------------------------------------------------------------
// Kernel 3: main GEMM with gather.
//   out[row][c] = sum_d x[b][gather[row]][d] * WcT[d][c] + cvec[c]
// Full WcT staged in SMEM (147.5 KB), A streamed in 128x64 tiles.
// Thread (tx,ty): tx in [0,16) -> 3 cols, ty in [0,16) -> 8 rows.
// ---------------------------------------------------------------------------
#define SMEM_W   (D_ * NPAD)                 // 36864 floats
#define A_LD     (BK + 1)                    // padded lda for aS
#define SMEM_A   (BM * A_LD)                 // 8320 floats
#define SMEM_FLOATS (SMEM_W + SMEM_A + NPAD)
#define SMEM_BYTES  (SMEM_FLOATS * 4 + BM * 4)

extern "C" __global__ void __launch_bounds__(THREADS, 1)
gemm_kernel(const float* __restrict__ x,
            float* __restrict__ out) {
    extern __shared__ float smem[];
    float* wS = smem;                       // [768][48]
    float* aS = smem + SMEM_W;              // [128][65]
    float* cS = aS + SMEM_A;                // [48]
    int*   gS = (int*)(cS + NPAD);          // [128]

    const int tid = threadIdx.x;
    const int row0 = blockIdx.x * BM;

    // Stage full WcT (coalesced, float4)
    {
        const float4* src = (const float4*)g_WcT;
        float4* dst = (float4*)wS;
#pragma unroll
        for (int i = tid; i < SMEM_W / 4; i += THREADS) dst[i] = src[i];
    }
    if (tid < NPAD) cS[tid] = g_cvec[tid];
    if (tid < BM) gS[tid] = g_gather[row0 + tid];
    __syncthreads();

    const int tx = tid & 15;    // col group: cols 3*tx .. 3*tx+2
    const int ty = tid >> 4;    // row group: rows 8*ty .. 8*ty+7

    float acc[8][3];
#pragma unroll
    for (int r = 0; r < 8; r++) { acc[r][0] = 0.f; acc[r][1] = 0.f; acc[r][2] = 0.f; }

    const float* wBase = wS + tx * 3;

    for (int k0 = 0; k0 < D_; k0 += BK) {
        // Load A tile: 128 rows x 64 k, gathered rows; zeros for invalid rows.
        // Each thread: 2 float4 chunks per pass -> 8192/256/4 = 8 float4.
#pragma unroll
        for (int i = tid; i < BM * (BK / 4); i += THREADS) {
            const int r = i >> 4;            // i / 16
            const int q = i & 15;            // float4 index within 64-k row
            const int src = gS[r];
            float4 v = make_float4(0.f, 0.f, 0.f, 0.f);
            if (src >= 0) {
                const int b = (row0 + r) / L_;
                v = *(const float4*)(x + ((long)b * L_ + src) * D_ + k0 + q * 4);
            }
            float* dstp = aS + r * A_LD + q * 4;
            dstp[0] = v.x; dstp[1] = v.y; dstp[2] = v.z; dstp[3] = v.w;
        }
        __syncthreads();

        const float* wp = wBase + (long)k0 * NPAD;
        const float* ap = aS + ty * 8 * A_LD;
#pragma unroll 16
        for (int kk = 0; kk < BK; kk++) {
            const float w0 = wp[kk * NPAD + 0];
            const float w1 = wp[kk * NPAD + 1];
            const float w2 = wp[kk * NPAD + 2];
#pragma unroll
            for (int r = 0; r < 8; r++) {
                const float a = ap[r * A_LD + kk];
                acc[r][0] = fmaf(a, w0, acc[r][0]);
                acc[r][1] = fmaf(a, w1, acc[r][1]);
                acc[r][2] = fmaf(a, w2, acc[r][2]);
            }
        }
        __syncthreads();
    }

    // Epilogue: out[row][c] = acc + cvec[c]; invalid rows have acc==0 -> cvec.
    const float c0 = cS[tx * 3 + 0];
    const float c1 = cS[tx * 3 + 1];
    const float c2 = (tx * 3 + 2 < NPAD) ? cS[tx * 3 + 2] : 0.f;
#pragma unroll
    for (int r = 0; r < 8; r++) {
        const long row = row0 + ty * 8 + r;
        float* o = out + row * C_;
        const int cbase = tx * 3;
        if (cbase + 0 < C_) o[cbase + 0] = acc[r][0] + c0;
        if (cbase + 1 < C_) o[cbase + 1] = acc[r][1] + c1;
        if (cbase + 2 < C_) o[cbase + 2] = acc[r][2] + c2;
    }
}

// ---------------------------------------------------------------------------
extern "C" void kernel_launch(void* const* d_in, const int* in_sizes, int n_in,
                              void* d_out, int out_size) {
    const float* x   = (const float*)d_in[0];   // (32,512,768) f32
    const int*   vid = (const int*)  d_in[1];   // (32,512) i32
    const float* W1  = (const float*)d_in[2];   // (100,768)
    const float* b1  = (const float*)d_in[3];   // (100,)
    const float* W2  = (const float*)d_in[4];   // (45,100)
    const float* b2  = (const float*)d_in[5];   // (45,)
    float* out = (float*)d_out;                  // (16384,45)

    static bool attr_set = false;
    if (!attr_set) {
        cudaFuncSetAttribute(gemm_kernel,
                             cudaFuncAttributeMaxDynamicSharedMemorySize,
                             SMEM_BYTES);
        attr_set = true;
    }

    compact_kernel<<<B_, L_>>>(vid);
    fuse_kernel<<<D_, NPAD>>>(W1, b1, W2, b2);
    gemm_kernel<<<M_ / BM, THREADS, SMEM_BYTES>>>(x, out);
}

// round 2
// speedup vs baseline: 1.8652x; 1.8652x over previous
#include <cuda_runtime.h>
#include <cstdint>

// Problem shape (fixed)
#define B_  32
#define L_  512
#define D_  768
#define H_  100
#define C_  45
#define M_  (B_ * L_)          // 16384 rows
#define NPAD 48                // padded cols
#define WSTR 772               // wS row stride (c-major), floats (768 + 4 pad)
#define BM 64                  // rows per GEMM block
#define BK 64                  // k chunk
#define ALD 68                 // aS row stride (floats), mult of 4
#define NCHUNK (D_ / BK)       // 12
#define GTHREADS 256
#define PTHREADS 512

// Device scratch (no allocation allowed)
__device__ float g_WcT[NPAD * WSTR];   // fused weight, c-major [c][d] padded
__device__ float g_cvec[NPAD];         // W2@b1 + b2
__device__ int   g_gather[M_];         // compacted source index or -1

// fma on packed f32x2 (FFMA2)
#define FMA2(d, a, b) asm("fma.rn.f32x2 %0, %1, %2, %3;" : "=l"(d) : "l"(a), "l"(b), "l"(d))

// ---------------------------------------------------------------------------
// Prep: blocks 0..31 -> compaction (ballot scan), blocks 32..103 -> weight fuse
// ---------------------------------------------------------------------------
__global__ void __launch_bounds__(PTHREADS)
prep_kernel(const int* __restrict__ valid_ids,
            const float* __restrict__ W1,
            const float* __restrict__ b1,
            const float* __restrict__ W2,
            const float* __restrict__ b2) {
    const int t = threadIdx.x;
    if (blockIdx.x < B_) {
        // ---- compaction for batch b ----
        __shared__ int wsum[16];
        const int b = blockIdx.x;
        const int v = (valid_ids[b * L_ + t] == 1);
        const unsigned mask = __ballot_sync(0xffffffffu, v);
        const int lane = t & 31, wid = t >> 5;
        const int wprefix = __popc(mask & ((1u << lane) - 1u));
        if (lane == 0) wsum[wid] = __popc(mask);
        g_gather[b * L_ + t] = -1;
        __syncthreads();
        if (t < 16) {
            int x = wsum[t];
#pragma unroll
            for (int off = 1; off < 16; off <<= 1) {
                int y = __shfl_up_sync(0xffffu, x, off);
                if (t >= off) x += y;
            }
            wsum[t] = x;
        }
        __syncthreads();
        const int base = (wid == 0) ? 0 : wsum[wid - 1];
        if (v) g_gather[b * L_ + base + wprefix] = t;
    } else {
        // ---- weight fuse: WcT[c][d] = sum_h W2[c][h] * W1[h][d] ----
        const int gidx = (blockIdx.x - B_) * PTHREADS + t;   // 0..36863
        const int c = gidx / D_;
        const int d = gidx - c * D_;
        float s = 0.0f;
        if (c < C_) {
#pragma unroll 4
            for (int h = 0; h < H_; h++)
                s += W2[c * H_ + h] * W1[h * D_ + d];
        }
        g_WcT[c * WSTR + d] = s;
        if (blockIdx.x == B_ && t < NPAD) {
            float cv = 0.0f;
            if (t < C_) {
                for (int h = 0; h < H_; h++) cv += W2[t * H_ + h] * b1[h];
                cv += b2[t];
            }
            g_cvec[t] = cv;
        }
    }
}

// ---------------------------------------------------------------------------
// GEMM: out[row][c] = sum_d x[b][gather[row]][d] * Wc[c][d] + cvec[c]
// 256 blocks of 64 rows; blocks with no valid rows just write cvec and exit.
// Thread (tx 0..15 -> 3 cols, ty 0..15 -> 4 rows), f32x2 packed along k.
// ---------------------------------------------------------------------------
#define SMEM_W  (NPAD * WSTR)            // 37056 floats
#define SMEM_A  (2 * BM * ALD)           // 8704 floats (double buffered)
#define SMEM_FLOATS (SMEM_W + SMEM_A + NPAD)
#define SMEM_BYTES (SMEM_FLOATS * 4 + BM * 4)

extern "C" __global__ void __launch_bounds__(GTHREADS, 1)
gemm_kernel(const float* __restrict__ x, float* __restrict__ out) {
    extern __shared__ float smem[];
    float* wS = smem;                    // [48][772] c-major
    float* aS = smem + SMEM_W;           // 2 x [64][68]
    float* cS = aS + SMEM_A;             // [48]
    int*   gS = (int*)(cS + NPAD);       // [64]

    const int tid  = threadIdx.x;
    const int row0 = blockIdx.x * BM;

    if (tid < BM)   gS[tid] = g_gather[row0 + tid];
    if (tid < NPAD) cS[tid] = g_cvec[tid];
    __syncthreads();

    // Fully-invalid block: output is the constant vector.
    if (gS[0] < 0) {
        float* o = out + (size_t)row0 * C_;
        for (int i = tid; i < BM * C_; i += GTHREADS)
            o[i] = cS[i % C_];
        return;
    }

    const int b = row0 / L_;
    const float* xb = x + (size_t)b * L_ * D_;
    const int q = tid & 15;              // float4 index within 64-k row

    // Per-thread gathered row sources for A staging (rows r = tid>>4 + 16j)
    const float* xrow[4];
#pragma unroll
    for (int j = 0; j < 4; j++) {
        const int r = (tid >> 4) + 16 * j;
        const int s = gS[r];
        xrow[j] = (s >= 0) ? (xb + (size_t)s * D_) : nullptr;
    }

    // Prefetch A chunk 0 (long-latency LDG first)
    float4 pf[4];
#pragma unroll
    for (int j = 0; j < 4; j++)
        pf[j] = xrow[j] ? *(const float4*)(xrow[j] + q * 4)
                        : make_float4(0.f, 0.f, 0.f, 0.f);

    // Stage full Wc (identical padded layout in global and smem: linear copy)
    {
        const float4* s4 = (const float4*)g_WcT;
        float4* d4 = (float4*)wS;
        for (int i = tid; i < SMEM_W / 4; i += GTHREADS) d4[i] = s4[i];
    }
    // Store A chunk 0
#pragma unroll
    for (int j = 0; j < 4; j++) {
        const int r = (tid >> 4) + 16 * j;
        *(float4*)(aS + r * ALD + q * 4) = pf[j];
    }
    __syncthreads();

    const int tx = tid & 15;             // cols 3tx .. 3tx+2
    const int ty = tid >> 4;             // rows 4ty .. 4ty+3

    unsigned long long acc[4][3];
#pragma unroll
    for (int r = 0; r < 4; r++)
#pragma unroll
        for (int c = 0; c < 3; c++) acc[r][c] = 0ull;

    const float* w0b = wS + (3 * tx + 0) * WSTR;
    const float* w1b = wS + (3 * tx + 1) * WSTR;
    const float* w2b = wS + (3 * tx + 2) * WSTR;

    for (int ch = 0; ch < NCHUNK; ch++) {
        // Prefetch next A chunk
        if (ch < NCHUNK - 1) {
            const int k0n = (ch + 1) * BK;
#pragma unroll
            for (int j = 0; j < 4; j++)
                pf[j] = xrow[j] ? *(const float4*)(xrow[j] + k0n + q * 4)
                                : make_float4(0.f, 0.f, 0.f, 0.f);
        }

        const float* ab = aS + (ch & 1) * BM * ALD + (ty * 4) * ALD;
        const float* wc0 = w0b + ch * BK;
        const float* wc1 = w1b + ch * BK;
        const float* wc2 = w2b + ch * BK;

#pragma unroll
        for (int s = 0; s < BK / 4; s++) {     // 16 steps of 4 k each
            const ulonglong2 a0 = *(const ulonglong2*)(ab + 0 * ALD + 4 * s);
            const ulonglong2 a1 = *(const ulonglong2*)(ab + 1 * ALD + 4 * s);
            const ulonglong2 a2 = *(const ulonglong2*)(ab + 2 * ALD + 4 * s);
            const ulonglong2 a3 = *(const ulonglong2*)(ab + 3 * ALD + 4 * s);
            const ulonglong2 w0 = *(const ulonglong2*)(wc0 + 4 * s);
            const ulonglong2 w1 = *(const ulonglong2*)(wc1 + 4 * s);
            const ulonglong2 w2 = *(const ulonglong2*)(wc2 + 4 * s);

            FMA2(acc[0][0], a0.x, w0.x); FMA2(acc[0][0], a0.y, w0.y);
            FMA2(acc[0][1], a0.x, w1.x); FMA2(acc[0][1], a0.y, w1.y);
            FMA2(acc[0][2], a0.x, w2.x); FMA2(acc[0][2], a0.y, w2.y);
            FMA2(acc[1][0], a1.x, w0.x); FMA2(acc[1][0], a1.y, w0.y);
            FMA2(acc[1][1], a1.x, w1.x); FMA2(acc[1][1], a1.y, w1.y);
            FMA2(acc[1][2], a1.x, w2.x); FMA2(acc[1][2], a1.y, w2.y);
            FMA2(acc[2][0], a2.x, w0.x); FMA2(acc[2][0], a2.y, w0.y);
            FMA2(acc[2][1], a2.x, w1.x); FMA2(acc[2][1], a2.y, w1.y);
            FMA2(acc[2][2], a2.x, w2.x); FMA2(acc[2][2], a2.y, w2.y);
            FMA2(acc[3][0], a3.x, w0.x); FMA2(acc[3][0], a3.y, w0.y);
            FMA2(acc[3][1], a3.x, w1.x); FMA2(acc[3][1], a3.y, w1.y);
            FMA2(acc[3][2], a3.x, w2.x); FMA2(acc[3][2], a3.y, w2.y);
        }

        if (ch < NCHUNK - 1) {
            float* nb = aS + ((ch + 1) & 1) * BM * ALD;
#pragma unroll
            for (int j = 0; j < 4; j++) {
                const int r = (tid >> 4) + 16 * j;
                *(float4*)(nb + r * ALD + q * 4) = pf[j];
            }
            __syncthreads();
        }
    }

    // Epilogue: reduce f32x2 halves, add cvec, store cols < 45 (tx==15 -> none)
    const int cb = 3 * tx;
#pragma unroll
    for (int r = 0; r < 4; r++) {
        float* o = out + (size_t)(row0 + ty * 4 + r) * C_;
#pragma unroll
        for (int c = 0; c < 3; c++) {
            if (cb + c < C_) {
                const unsigned long long v = acc[r][c];
                const float lo = __uint_as_float((unsigned)(v & 0xffffffffu));
                const float hi = __uint_as_float((unsigned)(v >> 32));
                o[cb + c] = lo + hi + cS[cb + c];
            }
        }
    }
}

// ---------------------------------------------------------------------------
extern "C" void kernel_launch(void* const* d_in, const int* in_sizes, int n_in,
                              void* d_out, int out_size) {
    const float* x   = (const float*)d_in[0];   // (32,512,768) f32
    const int*   vid = (const int*)  d_in[1];   // (32,512) i32
    const float* W1  = (const float*)d_in[2];   // (100,768)
    const float* b1  = (const float*)d_in[3];   // (100,)
    const float* W2  = (const float*)d_in[4];   // (45,100)
    const float* b2  = (const float*)d_in[5];   // (45,)
    float* out = (float*)d_out;                 // (16384,45)

    static bool attr_set = false;
    if (!attr_set) {
        cudaFuncSetAttribute(gemm_kernel,
                             cudaFuncAttributeMaxDynamicSharedMemorySize,
                             SMEM_BYTES);
        attr_set = true;
    }

    prep_kernel<<<B_ + (NPAD * D_) / PTHREADS, PTHREADS>>>(vid, W1, b1, W2, b2);
    gemm_kernel<<<M_ / BM, GTHREADS, SMEM_BYTES>>>(x, out);
}